// round 10
// baseline (speedup 1.0000x reference)
#include <cuda_runtime.h>
#include <cuda_fp16.h>
#include <math.h>
#include <stdint.h>

#define BATCH 8
#define CIN   256
#define NPIX  16384
#define HEADS 4
#define DH    32
#define HID   128

// ---------------- scratch (device globals; no allocation allowed) ------------
__device__ __half g_kvh[(long)BATCH * 256 * NPIX];    // k rows 0..127, v rows 128..255 (fp16)
__device__ __half g_wh[256 * 256];                    // W_kv in fp16
__device__ __half g_wtoth[BATCH * 256 * 256];         // per-batch effective weight (fp16)
__device__ float  g_ctx[BATCH * HEADS * DH * DH];     // 32768 elements
__device__ float  g_z[BATCH * HEADS * DH];            // 1024 elements
__device__ float  g_weff[BATCH * 256 * HID];

__device__ __forceinline__ uint32_t cvt_tf32(float x) {
    uint32_t u;
    asm("cvt.rna.tf32.f32 %0, %1;" : "=r"(u) : "f"(x));
    return u;
}
__device__ __forceinline__ uint32_t smem_u32(const void* p) {
    uint32_t a;
    asm("{ .reg .u64 t; cvta.to.shared.u64 t, %1; cvt.u32.u64 %0, t; }" : "=r"(a) : "l"(p));
    return a;
}
#define CP16(dst, src) \
    asm volatile("cp.async.cg.shared.global [%0], [%1], 16;" :: "r"(dst), "l"(src) : "memory")

// ---------------- init: zero ALL accumulators + convert W_kv to fp16 ---------
// Grid MUST cover BATCH*HEADS*DH*DH = 32768 (cross-call determinism!).
__global__ void k_init(const float* __restrict__ wkv) {
    int i = blockIdx.x * blockDim.x + threadIdx.x;   // 128*256 = 32768
    if (i < 16384) {                                  // W_kv: 65536 f32 = 16384 float4
        float4 v = ((const float4*)wkv)[i];
        __half2 h0 = __floats2half2_rn(v.x, v.y);
        __half2 h1 = __floats2half2_rn(v.z, v.w);
        uint2 u = { *(uint32_t*)&h0, *(uint32_t*)&h1 };
        ((uint2*)g_wh)[i] = u;
    }
    g_ctx[i] = 0.f;                                   // all 32768
    if (i < BATCH * HEADS * DH) g_z[i] = 0.f;         // 1024
}

// =============================================================================
// fp16-mma GEMM with fp32 B streamed via cp.async and converted at fragment
// load (direct LDS + cvt, conflict-free). C[b] = A[b](fp16) @ X[b](fp32).
// BM=BN=128, BK=64, 2-stage, 256 thr (8 warps 2x4), warp tile 64x32.
// =============================================================================
#define A_BUF 18432              // 128 rows * 144B (64 halves + 8 pad)
#define BF_LDW 132               // B stage row stride in floats (128 + 4 pad)
#define B_BUF (64 * BF_LDW * 4)  // 64 k-rows * 528B = 33792
#define SMEM_G (2 * A_BUF + 2 * B_BUF)   // 104448

__device__ __forceinline__ void g2s_tile(uint32_t sb, int buf,
                                         const __half* Arow, const float* Xb,
                                         long n0, int k0) {
    int tid = threadIdx.x;
    uint32_t abase = sb + buf * A_BUF;
    uint32_t bbase = sb + 2 * A_BUF + buf * B_BUF;
#pragma unroll
    for (int i = 0; i < 4; i++) {          // A: 128 rows x 64k fp16 = 1024 x 16B
        int f = i * 256 + tid;
        int r = f >> 3, c = f & 7;
        CP16(abase + r * 144 + c * 16, Arow + (long)r * 256 + k0 + c * 8);
    }
#pragma unroll
    for (int i = 0; i < 8; i++) {          // B: 64 k-rows x 128n fp32 = 2048 x 16B
        int f = i * 256 + tid;
        int r = f >> 5, c = f & 31;
        CP16(bbase + r * (BF_LDW * 4) + c * 16, Xb + (long)(k0 + r) * NPIX + n0 + c * 4);
    }
    asm volatile("cp.async.commit_group;" ::: "memory");
}

__global__ __launch_bounds__(256, 2)
void k_hgemm_async(const __half* __restrict__ A, long sA,
                   const float* __restrict__ X, long sX,
                   void* __restrict__ Cv, long sC,
                   const float* __restrict__ bias, int half_out)
{
    extern __shared__ char smem[];
    uint32_t sb = smem_u32(smem);

    int b = blockIdx.z;
    const __half* Ab = A + (long)b * sA + (long)blockIdx.y * 128 * 256;
    const float*  Xb = X + (long)b * sX;
    long n0 = (long)blockIdx.x * 128;
    int m0 = blockIdx.y * 128;

    int tid  = threadIdx.x;
    int wid  = tid >> 5, lane = tid & 31;
    int g4   = lane >> 2, q = lane & 3;
    int wm   = (wid >> 2) * 64;
    int wn   = (wid & 3) * 32;
    int rowoff = (lane & 7) + ((lane >> 3) & 1) * 8;
    int colsel = (lane >> 4) * 8;

    float acc[4][4][4];
#pragma unroll
    for (int i = 0; i < 4; i++)
#pragma unroll
        for (int j = 0; j < 4; j++)
#pragma unroll
            for (int r = 0; r < 4; r++) acc[i][j][r] = 0.f;

    g2s_tile(sb, 0, Ab, Xb, n0, 0);

#pragma unroll 1
    for (int t = 0; t < 4; t++) {
        if (t < 3) g2s_tile(sb, (t + 1) & 1, Ab, Xb, n0, (t + 1) * 64);
        if (t < 3) { asm volatile("cp.async.wait_group 1;" ::: "memory"); }
        else       { asm volatile("cp.async.wait_group 0;" ::: "memory"); }
        __syncthreads();

        uint32_t abase = sb + (t & 1) * A_BUF;
        const float* Bst = (const float*)(smem + 2 * A_BUF + (t & 1) * B_BUF);
#pragma unroll
        for (int ks = 0; ks < 64; ks += 16) {
            uint32_t af[4][4];
#pragma unroll
            for (int mf = 0; mf < 4; mf++) {
                uint32_t addr = abase + (uint32_t)((wm + mf * 16 + rowoff) * 144
                                                   + (ks + colsel) * 2);
                asm volatile(
                    "ldmatrix.sync.aligned.m8n8.x4.shared.b16 {%0,%1,%2,%3}, [%4];"
                    : "=r"(af[mf][0]), "=r"(af[mf][1]), "=r"(af[mf][2]), "=r"(af[mf][3])
                    : "r"(addr));
            }
#pragma unroll
            for (int nf = 0; nf < 4; nf++) {
                int n = wn + nf * 8 + g4;
                float x0 = Bst[(ks + 2 * q)     * BF_LDW + n];
                float x1 = Bst[(ks + 2 * q + 1) * BF_LDW + n];
                float x2 = Bst[(ks + 2 * q + 8) * BF_LDW + n];
                float x3 = Bst[(ks + 2 * q + 9) * BF_LDW + n];
                __half2 hb0 = __floats2half2_rn(x0, x1);
                __half2 hb1 = __floats2half2_rn(x2, x3);
                uint32_t b0 = *(uint32_t*)&hb0;
                uint32_t b1 = *(uint32_t*)&hb1;
#pragma unroll
                for (int mf = 0; mf < 4; mf++) {
                    asm volatile(
                        "mma.sync.aligned.m16n8k16.row.col.f32.f16.f16.f32 "
                        "{%0,%1,%2,%3},{%4,%5,%6,%7},{%8,%9},{%0,%1,%2,%3};"
                        : "+f"(acc[mf][nf][0]), "+f"(acc[mf][nf][1]),
                          "+f"(acc[mf][nf][2]), "+f"(acc[mf][nf][3])
                        : "r"(af[mf][0]), "r"(af[mf][1]),
                          "r"(af[mf][2]), "r"(af[mf][3]),
                          "r"(b0), "r"(b1));
                }
            }
        }
        __syncthreads();
    }

    if (half_out) {
        __half* Ch = (__half*)Cv + (long)b * sC;
#pragma unroll
        for (int mf = 0; mf < 4; mf++) {
            long mrow = m0 + wm + mf * 16 + g4;
#pragma unroll
            for (int nf = 0; nf < 4; nf++) {
                long nc = n0 + wn + nf * 8 + 2 * q;
                *(__half2*)&Ch[mrow * NPIX + nc] =
                    __floats2half2_rn(acc[mf][nf][0], acc[mf][nf][1]);
                *(__half2*)&Ch[(mrow + 8) * NPIX + nc] =
                    __floats2half2_rn(acc[mf][nf][2], acc[mf][nf][3]);
            }
        }
    } else {
        float* Cf = (float*)Cv + (long)b * sC;
#pragma unroll
        for (int mf = 0; mf < 4; mf++) {
            long mrow = m0 + wm + mf * 16 + g4;
            float bv0 = bias ? bias[mrow]     : 0.f;
            float bv1 = bias ? bias[mrow + 8] : 0.f;
#pragma unroll
            for (int nf = 0; nf < 4; nf++) {
                long nc = n0 + wn + nf * 8 + 2 * q;
                float2 v0 = { acc[mf][nf][0] + bv0, acc[mf][nf][1] + bv0 };
                float2 v1 = { acc[mf][nf][2] + bv1, acc[mf][nf][3] + bv1 };
                *(float2*)&Cf[mrow * NPIX + nc]       = v0;
                *(float2*)&Cf[(mrow + 8) * NPIX + nc] = v1;
            }
        }
    }
}

// =============================================================================
// Tensor-core context (unchanged, passing, 23.6us)
// =============================================================================
#define CTX_ESZ 8704           // 32 rows * 136 halves * 2B
#define CTX_SMEM (8 * CTX_ESZ) // 69632

__global__ __launch_bounds__(128)
void k_context_mma()
{
    extern __shared__ char smem[];
    int tid = threadIdx.x, wid = tid >> 5, lane = tid & 31;
    int b = blockIdx.z, h = blockIdx.y;
    int g4 = lane >> 2, q = lane & 3;

    __half* Ew = (__half*)(smem + wid * CTX_ESZ);
    __half* Vw = (__half*)(smem + 4 * CTX_ESZ + wid * CTX_ESZ);

    const __half* kb = g_kvh + (long)(b * 256 + h * 32) * NPIX;
    const __half* vb = kb + (long)128 * NPIX;

    long n0 = (long)blockIdx.x * 512 + wid * 128;

    int lr = lane >> 4;
    int lc = (lane & 15) * 8;
#pragma unroll
    for (int i = 0; i < 16; i++) {
        int r = 2 * i + lr;
        long off = (long)r * NPIX + n0 + lc;
        uint4 ku = *(const uint4*)&kb[off];
        uint4 vu = *(const uint4*)&vb[off];
        const __half2* kh = (const __half2*)&ku;
        uint4 eu;
        __half2* eh = (__half2*)&eu;
#pragma unroll
        for (int j = 0; j < 4; j++) {
            float2 f = __half22float2(kh[j]);
            eh[j] = __floats2half2_rn(__expf(f.x), __expf(f.y));
        }
        *(uint4*)&Ew[r * 136 + lc] = eu;
        *(uint4*)&Vw[r * 136 + lc] = vu;
    }
    __syncwarp();

    float acc[2][4][4];
#pragma unroll
    for (int i = 0; i < 2; i++)
#pragma unroll
        for (int j = 0; j < 4; j++)
#pragma unroll
            for (int r = 0; r < 4; r++) acc[i][j][r] = 0.f;
    float zac[2][4];
#pragma unroll
    for (int i = 0; i < 2; i++)
#pragma unroll
        for (int r = 0; r < 4; r++) zac[i][r] = 0.f;

    const uint32_t ONES = 0x3C003C00u;

#pragma unroll
    for (int ks = 0; ks < 128; ks += 16) {
        int fc = ks + 2 * q;
#pragma unroll
        for (int mf = 0; mf < 2; mf++) {
            int d0 = mf * 16 + g4;
            uint32_t a0 = *(const uint32_t*)&Ew[d0 * 136 + fc];
            uint32_t a1 = *(const uint32_t*)&Ew[(d0 + 8) * 136 + fc];
            uint32_t a2 = *(const uint32_t*)&Ew[d0 * 136 + fc + 8];
            uint32_t a3 = *(const uint32_t*)&Ew[(d0 + 8) * 136 + fc + 8];
            asm volatile(
                "mma.sync.aligned.m16n8k16.row.col.f32.f16.f16.f32 "
                "{%0,%1,%2,%3},{%4,%5,%6,%7},{%8,%9},{%0,%1,%2,%3};"
                : "+f"(zac[mf][0]), "+f"(zac[mf][1]),
                  "+f"(zac[mf][2]), "+f"(zac[mf][3])
                : "r"(a0), "r"(a1), "r"(a2), "r"(a3),
                  "r"(ONES), "r"(ONES));
#pragma unroll
            for (int nf = 0; nf < 4; nf++) {
                int e0r = nf * 8 + g4;
                uint32_t b0 = *(const uint32_t*)&Vw[e0r * 136 + fc];
                uint32_t b1 = *(const uint32_t*)&Vw[e0r * 136 + fc + 8];
                asm volatile(
                    "mma.sync.aligned.m16n8k16.row.col.f32.f16.f16.f32 "
                    "{%0,%1,%2,%3},{%4,%5,%6,%7},{%8,%9},{%0,%1,%2,%3};"
                    : "+f"(acc[mf][nf][0]), "+f"(acc[mf][nf][1]),
                      "+f"(acc[mf][nf][2]), "+f"(acc[mf][nf][3])
                    : "r"(a0), "r"(a1), "r"(a2), "r"(a3),
                      "r"(b0), "r"(b1));
            }
        }
    }
    __syncwarp();

    if (q == 0) {
        float* zp = g_z + (b * HEADS + h) * DH;
        atomicAdd(&zp[g4],      zac[0][0]);
        atomicAdd(&zp[g4 + 8],  zac[0][2]);
        atomicAdd(&zp[g4 + 16], zac[1][0]);
        atomicAdd(&zp[g4 + 24], zac[1][2]);
    }

    float* red = (float*)(smem + wid * CTX_ESZ);
#pragma unroll
    for (int mf = 0; mf < 2; mf++)
#pragma unroll
        for (int nf = 0; nf < 4; nf++) {
            int dd = mf * 16 + g4, ee = nf * 8 + 2 * q;
            red[dd * 32 + ee]           = acc[mf][nf][0];
            red[dd * 32 + ee + 1]       = acc[mf][nf][1];
            red[(dd + 8) * 32 + ee]     = acc[mf][nf][2];
            red[(dd + 8) * 32 + ee + 1] = acc[mf][nf][3];
        }
    __syncthreads();

    float* cp = g_ctx + (long)(b * HEADS + h) * 1024;
    const float* r0 = (const float*)(smem);
    const float* r1 = (const float*)(smem + CTX_ESZ);
    const float* r2 = (const float*)(smem + 2 * CTX_ESZ);
    const float* r3 = (const float*)(smem + 3 * CTX_ESZ);
#pragma unroll
    for (int j = tid; j < 1024; j += 128) {
        float s = (r0[j] + r1[j]) + (r2[j] + r3[j]);
        atomicAdd(&cp[j], s);
    }
}

// ---------------- tf32 mma SGEMM -> fp16 out (tiny fold GEMM, unchanged) -----
__global__ __launch_bounds__(256, 2)
void k_sgemm_tc(const float* __restrict__ A, long sA,
                const float* __restrict__ X, long sX,
                __half* __restrict__ C, long sC,
                int M, int K, int N)
{
    const int BM = 128, BN = 128, BK = 32;
    __shared__ uint32_t As[BK][BM + 4];
    __shared__ uint32_t Bs[BK][BN + 4];

    int b = blockIdx.z;
    const float* Ab = A + (long)b * sA;
    const float* Xb = X + (long)b * sX;
    __half*      Cb = C + (long)b * sC;
    int m0 = blockIdx.y * BM, n0 = blockIdx.x * BN;
    int tid  = threadIdx.x;
    int wid  = tid >> 5, lane = tid & 31;
    int g4   = lane >> 2, q = lane & 3;
    int wm   = (wid >> 2) * 64;
    int wn   = (wid & 3) * 32;

    float acc[4][4][4];
#pragma unroll
    for (int i = 0; i < 4; i++)
#pragma unroll
        for (int j = 0; j < 4; j++)
#pragma unroll
            for (int r = 0; r < 4; r++) acc[i][j][r] = 0.f;

    for (int k0 = 0; k0 < K; k0 += BK) {
#pragma unroll
        for (int i = 0; i < 4; i++) {
            int f  = i * 256 + tid;
            int m  = f >> 3, k4 = (f & 7) << 2;
            float4 v = *(const float4*)&Ab[(long)(m0 + m) * K + k0 + k4];
            As[k4 + 0][m] = cvt_tf32(v.x); As[k4 + 1][m] = cvt_tf32(v.y);
            As[k4 + 2][m] = cvt_tf32(v.z); As[k4 + 3][m] = cvt_tf32(v.w);
        }
#pragma unroll
        for (int i = 0; i < 4; i++) {
            int f  = i * 256 + tid;
            int kk = f >> 5, n4 = (f & 31) << 2;
            float4 v = *(const float4*)&Xb[(long)(k0 + kk) * N + n0 + n4];
            uint4 u;
            u.x = cvt_tf32(v.x); u.y = cvt_tf32(v.y);
            u.z = cvt_tf32(v.z); u.w = cvt_tf32(v.w);
            *(uint4*)&Bs[kk][n4] = u;
        }
        __syncthreads();

#pragma unroll
        for (int ks = 0; ks < BK; ks += 8) {
            uint32_t af[4][4];
#pragma unroll
            for (int mf = 0; mf < 4; mf++) {
                int mb = wm + mf * 16;
                af[mf][0] = As[ks + q    ][mb + g4    ];
                af[mf][1] = As[ks + q    ][mb + g4 + 8];
                af[mf][2] = As[ks + q + 4][mb + g4    ];
                af[mf][3] = As[ks + q + 4][mb + g4 + 8];
            }
#pragma unroll
            for (int nf = 0; nf < 4; nf++) {
                int nb = wn + nf * 8;
                uint32_t b0 = Bs[ks + q    ][nb + g4];
                uint32_t b1 = Bs[ks + q + 4][nb + g4];
#pragma unroll
                for (int mf = 0; mf < 4; mf++) {
                    asm volatile(
                        "mma.sync.aligned.m16n8k8.row.col.f32.tf32.tf32.f32 "
                        "{%0,%1,%2,%3},{%4,%5,%6,%7},{%8,%9},{%0,%1,%2,%3};"
                        : "+f"(acc[mf][nf][0]), "+f"(acc[mf][nf][1]),
                          "+f"(acc[mf][nf][2]), "+f"(acc[mf][nf][3])
                        : "r"(af[mf][0]), "r"(af[mf][1]),
                          "r"(af[mf][2]), "r"(af[mf][3]),
                          "r"(b0), "r"(b1));
                }
            }
        }
        __syncthreads();
    }

#pragma unroll
    for (int mf = 0; mf < 4; mf++) {
        int mrow = m0 + wm + mf * 16 + g4;
#pragma unroll
        for (int nf = 0; nf < 4; nf++) {
            int nc = n0 + wn + nf * 8 + 2 * q;
            *(__half2*)&Cb[(long)mrow * N + nc] =
                __floats2half2_rn(acc[mf][nf][0], acc[mf][nf][1]);
            *(__half2*)&Cb[(long)(mrow + 8) * N + nc] =
                __floats2half2_rn(acc[mf][nf][2], acc[mf][nf][3]);
        }
    }
}

// ---------------- fold: W_eff[b][o][h*32+d] = sum_e w_out[o][h*32+e]*ctxn[h][d][e]
__global__ __launch_bounds__(256)
void k_weff(const float* __restrict__ w_out)
{
    __shared__ float ctxn[HEADS][DH][DH + 1];
    __shared__ float zinv[HEADS * DH];
    int b = blockIdx.x, oc = blockIdx.y;
    int tid = threadIdx.x;
    if (tid < 128) zinv[tid] = 1.0f / g_z[b * 128 + tid];
    __syncthreads();
    for (int i = tid; i < 4096; i += 256) {
        int h = i >> 10, d = (i >> 5) & 31, e = i & 31;
        ctxn[h][d][e] = g_ctx[b * 4096 + i] * zinv[h * 32 + d];
    }
    __syncthreads();
    for (int i = tid; i < 8 * 128; i += 256) {
        int ol = i >> 7;
        int hd = i & 127;
        int h = hd >> 5, d = hd & 31;
        int o = oc * 8 + ol;
        const float* wrow = w_out + o * HID + h * 32;
        float s = 0.f;
#pragma unroll
        for (int e = 0; e < 32; e++) s = fmaf(wrow[e], ctxn[h][d][e], s);
        g_weff[((long)b * 256 + o) * HID + hd] = s;
    }
}

// ---------------- launch --------------------------------------------------
extern "C" void kernel_launch(void* const* d_in, const int* in_sizes, int n_in,
                              void* d_out, int out_size)
{
    const float *x = nullptr, *w_qkv = nullptr, *w_out = nullptr, *b_out = nullptr;
    for (int i = 0; i < n_in; i++) {
        const float* p = (const float*)d_in[i];
        if      (in_sizes[i] == BATCH * CIN * NPIX) x     = p;
        else if (in_sizes[i] == 3 * HID * CIN)      w_qkv = p;
        else if (in_sizes[i] == CIN * HID)          w_out = p;
        else if (in_sizes[i] == CIN)                b_out = p;
    }
    float* out = (float*)d_out;

    __half *kvh, *wh, *wtoth;
    float *weff;
    cudaGetSymbolAddress((void**)&kvh,   g_kvh);
    cudaGetSymbolAddress((void**)&wh,    g_wh);
    cudaGetSymbolAddress((void**)&wtoth, g_wtoth);
    cudaGetSymbolAddress((void**)&weff,  g_weff);

    cudaFuncSetAttribute(k_hgemm_async,
                         cudaFuncAttributeMaxDynamicSharedMemorySize, SMEM_G);
    cudaFuncSetAttribute(k_context_mma,
                         cudaFuncAttributeMaxDynamicSharedMemorySize, CTX_SMEM);

    // 0) zero ALL accumulators (32768 threads) + convert W_kv
    k_init<<<128, 256>>>(w_qkv + 128 * CIN);

    // 1) kv = W_kv @ x  (fp16 mma, fp32 X streamed + converted in-kernel)
    k_hgemm_async<<<dim3(NPIX / 128, 2, BATCH), 256, SMEM_G>>>(
        wh, 0,
        x, (long)CIN * NPIX,
        kvh, (long)256 * NPIX,
        nullptr, 1);

    // 2) context via tensor cores
    k_context_mma<<<dim3(32, HEADS, BATCH), 128, CTX_SMEM>>>();

    // 3a) fold w_out with normalized context -> W_eff (fp32)
    k_weff<<<dim3(BATCH, 32), 256>>>(w_out);

    // 3b) W_total[b] = W_eff[b] @ W_q  -> fp16 wtot
    k_sgemm_tc<<<dim3(2, 2, BATCH), 256>>>(
        weff, (long)256 * HID,
        w_qkv, 0,
        wtoth, (long)256 * 256,
        256, HID, 256);

    // 4) y[b] = W_total[b] @ x[b] + b_out  (fp16 mma, fp32 X in-kernel convert)
    k_hgemm_async<<<dim3(NPIX / 128, 2, BATCH), 256, SMEM_G>>>(
        wtoth, (long)256 * 256,
        x, (long)CIN * NPIX,
        out, (long)256 * NPIX,
        b_out, 0);
}

// round 11
// speedup vs baseline: 1.1062x; 1.1062x over previous
#include <cuda_runtime.h>
#include <cuda_fp16.h>
#include <math.h>
#include <stdint.h>

#define BATCH 8
#define CIN   256
#define NPIX  16384
#define HEADS 4
#define DH    32
#define HID   128

// ---------------- scratch (device globals; no allocation allowed) ------------
__device__ __half g_xh[(long)BATCH * CIN * NPIX];     // x in fp16 (written by k_fused1)
__device__ __half g_wh[256 * 256];                    // W_kv in fp16
__device__ __half g_wtoth[BATCH * 256 * 256];         // per-batch effective weight (fp16)
__device__ float  g_ctx[BATCH * HEADS * DH * DH];     // 32768
__device__ float  g_z[BATCH * HEADS * DH];            // 1024
__device__ float  g_weff[BATCH * 256 * HID];

__device__ __forceinline__ uint32_t cvt_tf32(float x) {
    uint32_t u;
    asm("cvt.rna.tf32.f32 %0, %1;" : "=r"(u) : "f"(x));
    return u;
}
__device__ __forceinline__ uint32_t smem_u32(const void* p) {
    uint32_t a;
    asm("{ .reg .u64 t; cvta.to.shared.u64 t, %1; cvt.u32.u64 %0, t; }" : "=r"(a) : "l"(p));
    return a;
}
#define CP16(dst, src) \
    asm volatile("cp.async.cg.shared.global [%0], [%1], 16;" :: "r"(dst), "l"(src) : "memory")
#define HMMA(acc, a0, a1, a2, a3, b0, b1) \
    asm volatile( \
        "mma.sync.aligned.m16n8k16.row.col.f32.f16.f16.f32 " \
        "{%0,%1,%2,%3},{%4,%5,%6,%7},{%8,%9},{%0,%1,%2,%3};" \
        : "+f"(acc[0]), "+f"(acc[1]), "+f"(acc[2]), "+f"(acc[3]) \
        : "r"(a0), "r"(a1), "r"(a2), "r"(a3), "r"(b0), "r"(b1))

// ---------------- init: zero ALL accumulators + convert W_kv to fp16 ---------
__global__ void k_init(const float* __restrict__ wkv) {
    int i = blockIdx.x * blockDim.x + threadIdx.x;   // 128*256 = 32768
    if (i < 16384) {
        float4 v = ((const float4*)wkv)[i];
        __half2 h0 = __floats2half2_rn(v.x, v.y);
        __half2 h1 = __floats2half2_rn(v.z, v.w);
        uint2 u = { *(uint32_t*)&h0, *(uint32_t*)&h1 };
        ((uint2*)g_wh)[i] = u;
    }
    g_ctx[i] = 0.f;
    if (i < BATCH * HEADS * DH) g_z[i] = 0.f;
}

// =============================================================================
// FUSED kernel: kv-GEMM + softmax-context, kv never hits DRAM.
//   CTA tile: 256 kv-channels x 128 pixels, K=256. 256 thr (8 warps 4Mx2N),
//   warp tile 64x64. A = W_kv fp16 (ldmatrix), B = x fp32 (cp.async staged,
//   fragment-converted). Also writes the converted fp16 x tile to g_xh.
//   Epilogue: acc -> smem fp16 (exp on k-half), per-head 32x32 ctx mma +
//   ones-mma z, block reduce, spread atomics.
// =============================================================================
#define F_AST   80                       // A row stride bytes (32 halves + 8 pad)
#define F_A_ST  (256 * F_AST)            // 20480 per stage
#define F_BLDW  132                      // B row stride floats (128 + 4 pad)
#define F_B_ST  (32 * F_BLDW * 4)        // 16896 per stage
#define F_B_OFF (2 * F_A_ST)
#define SMEM_F  (2 * F_A_ST + 2 * F_B_ST)  // 74752
#define EV_LDH  136                      // epilogue tile row stride (halves)

__global__ __launch_bounds__(256, 1)
void k_fused1(const __half* __restrict__ W, const float* __restrict__ X)
{
    extern __shared__ char smem[];
    uint32_t sb = smem_u32(smem);
    int tid = threadIdx.x, wid = tid >> 5, lane = tid & 31;
    int g4 = lane >> 2, q = lane & 3;
    int rowoff = (lane & 7) + ((lane >> 3) & 1) * 8;
    int colsel = (lane >> 4) * 8;
    int b = blockIdx.y;
    long n0 = (long)blockIdx.x * 128;
    const float* Xb = X + (long)b * CIN * NPIX;
    __half* XHb = g_xh + (long)b * CIN * NPIX;

    int wm = (wid >> 1) * 64;   // 0,64,128,192 (ch)
    int wn = (wid & 1) * 64;    // 0,64 (px)

    float acc[4][8][4];
#pragma unroll
    for (int i = 0; i < 4; i++)
#pragma unroll
        for (int j = 0; j < 8; j++)
#pragma unroll
            for (int r = 0; r < 4; r++) acc[i][j][r] = 0.f;

    // ---- stage loader
#define F_LOAD(buf, k0) do {                                                    \
        uint32_t abase_ = sb + (buf) * F_A_ST;                                  \
        uint32_t bbase_ = sb + F_B_OFF + (buf) * F_B_ST;                        \
        _Pragma("unroll")                                                       \
        for (int i_ = 0; i_ < 4; i_++) {                                        \
            int f_ = i_ * 256 + tid;                                            \
            int r_ = f_ >> 2, c_ = f_ & 3;                                      \
            CP16(abase_ + r_ * F_AST + c_ * 16, W + (long)r_ * 256 + (k0) + c_ * 8); \
        }                                                                       \
        _Pragma("unroll")                                                       \
        for (int i_ = 0; i_ < 4; i_++) {                                        \
            int f_ = i_ * 256 + tid;                                            \
            int r_ = f_ >> 5, c_ = f_ & 31;                                     \
            CP16(bbase_ + r_ * (F_BLDW * 4) + c_ * 16,                          \
                 Xb + (long)((k0) + r_) * NPIX + n0 + c_ * 4);                  \
        }                                                                       \
        asm volatile("cp.async.commit_group;" ::: "memory");                    \
    } while (0)

    F_LOAD(0, 0);

#pragma unroll 1
    for (int t = 0; t < 8; t++) {
        if (t < 7) F_LOAD((t + 1) & 1, (t + 1) * 32);
        if (t < 7) { asm volatile("cp.async.wait_group 1;" ::: "memory"); }
        else       { asm volatile("cp.async.wait_group 0;" ::: "memory"); }
        __syncthreads();

        const float* Bst = (const float*)(smem + F_B_OFF + (t & 1) * F_B_ST);

        // ---- emit converted fp16 x tile (each element written once globally)
#pragma unroll
        for (int i = 0; i < 2; i++) {
            int f = i * 256 + tid;
            int r = f >> 4, c = f & 15;
            const float* src = &Bst[r * F_BLDW + c * 8];
            uint4 u;
            __half2* uh = (__half2*)&u;
#pragma unroll
            for (int j = 0; j < 4; j++)
                uh[j] = __floats2half2_rn(src[2 * j], src[2 * j + 1]);
            *(uint4*)&XHb[(long)(t * 32 + r) * NPIX + n0 + c * 8] = u;
        }

        uint32_t abase = sb + (t & 1) * F_A_ST;
#pragma unroll
        for (int ks = 0; ks < 32; ks += 16) {
            uint32_t af[4][4];
#pragma unroll
            for (int mf = 0; mf < 4; mf++) {
                uint32_t addr = abase + (uint32_t)((wm + mf * 16 + rowoff) * F_AST
                                                   + (ks + colsel) * 2);
                asm volatile(
                    "ldmatrix.sync.aligned.m8n8.x4.shared.b16 {%0,%1,%2,%3}, [%4];"
                    : "=r"(af[mf][0]), "=r"(af[mf][1]), "=r"(af[mf][2]), "=r"(af[mf][3])
                    : "r"(addr));
            }
#pragma unroll
            for (int nf = 0; nf < 8; nf++) {
                int n = wn + nf * 8 + g4;
                float x0 = Bst[(ks + 2 * q)     * F_BLDW + n];
                float x1 = Bst[(ks + 2 * q + 1) * F_BLDW + n];
                float x2 = Bst[(ks + 2 * q + 8) * F_BLDW + n];
                float x3 = Bst[(ks + 2 * q + 9) * F_BLDW + n];
                __half2 hb0 = __floats2half2_rn(x0, x1);
                __half2 hb1 = __floats2half2_rn(x2, x3);
                uint32_t b0 = *(uint32_t*)&hb0;
                uint32_t b1 = *(uint32_t*)&hb1;
#pragma unroll
                for (int mf = 0; mf < 4; mf++)
                    HMMA(acc[mf][nf], af[mf][0], af[mf][1], af[mf][2], af[mf][3], b0, b1);
            }
        }
        __syncthreads();
    }

    // ===================== fused context epilogue =====================
    // 1) acc -> EV smem fp16; exp() applied to k-half (channels 0..127)
    __half* EV = (__half*)smem;
    int isk = (wm < 128);
#pragma unroll
    for (int mf = 0; mf < 4; mf++) {
        int mrow = wm + mf * 16 + g4;
#pragma unroll
        for (int nf = 0; nf < 8; nf++) {
            int nc = wn + nf * 8 + 2 * q;
            float v0 = acc[mf][nf][0], v1 = acc[mf][nf][1];
            float v2 = acc[mf][nf][2], v3 = acc[mf][nf][3];
            if (isk) {
                v0 = __expf(v0); v1 = __expf(v1);
                v2 = __expf(v2); v3 = __expf(v3);
            }
            *(__half2*)&EV[mrow * EV_LDH + nc]       = __floats2half2_rn(v0, v1);
            *(__half2*)&EV[(mrow + 8) * EV_LDH + nc] = __floats2half2_rn(v2, v3);
        }
    }
    __syncthreads();

    // 2) per-head ctx mma: warp = (head h, px-half p), 32x32 x 64px
    int h = wid >> 1, p = wid & 1;
    const __half* Ek = EV + (h * 32) * EV_LDH;
    const __half* Vv = EV + (128 + h * 32) * EV_LDH;
    float c2[2][4][4];
    float z2[2][4];
#pragma unroll
    for (int i = 0; i < 2; i++) {
#pragma unroll
        for (int j = 0; j < 4; j++)
#pragma unroll
            for (int r = 0; r < 4; r++) c2[i][j][r] = 0.f;
#pragma unroll
        for (int r = 0; r < 4; r++) z2[i][r] = 0.f;
    }
    const uint32_t ONES = 0x3C003C00u;

#pragma unroll
    for (int ks = 0; ks < 64; ks += 16) {
        int fc = p * 64 + ks + 2 * q;
#pragma unroll
        for (int mf = 0; mf < 2; mf++) {
            int d0 = mf * 16 + g4;
            uint32_t a0 = *(const uint32_t*)&Ek[d0 * EV_LDH + fc];
            uint32_t a1 = *(const uint32_t*)&Ek[(d0 + 8) * EV_LDH + fc];
            uint32_t a2 = *(const uint32_t*)&Ek[d0 * EV_LDH + fc + 8];
            uint32_t a3 = *(const uint32_t*)&Ek[(d0 + 8) * EV_LDH + fc + 8];
            HMMA(z2[mf], a0, a1, a2, a3, ONES, ONES);
#pragma unroll
            for (int nf = 0; nf < 4; nf++) {
                int e0 = nf * 8 + g4;
                uint32_t b0 = *(const uint32_t*)&Vv[e0 * EV_LDH + fc];
                uint32_t b1 = *(const uint32_t*)&Vv[e0 * EV_LDH + fc + 8];
                HMMA(c2[mf][nf], a0, a1, a2, a3, b0, b1);
            }
        }
    }
    __syncthreads();   // all EV reads done before overwrite

    // 3) z atomics (lanes q==0 hold column 0 of ones-mma)
    if (q == 0) {
        float* zp = g_z + (b * HEADS + h) * DH;
        atomicAdd(&zp[g4],      z2[0][0]);
        atomicAdd(&zp[g4 + 8],  z2[0][2]);
        atomicAdd(&zp[g4 + 16], z2[1][0]);
        atomicAdd(&zp[g4 + 24], z2[1][2]);
    }

    // 4) warp tiles -> smem, reduce px-halves, atomics
    float* red = (float*)smem + wid * 1024;
#pragma unroll
    for (int mf = 0; mf < 2; mf++)
#pragma unroll
        for (int nf = 0; nf < 4; nf++) {
            int dd = mf * 16 + g4, ee = nf * 8 + 2 * q;
            red[dd * 32 + ee]           = c2[mf][nf][0];
            red[dd * 32 + ee + 1]       = c2[mf][nf][1];
            red[(dd + 8) * 32 + ee]     = c2[mf][nf][2];
            red[(dd + 8) * 32 + ee + 1] = c2[mf][nf][3];
        }
    __syncthreads();

    const float* rall = (const float*)smem;
#pragma unroll
    for (int j = tid; j < 4096; j += 256) {
        int hh = j >> 10, e = j & 1023;
        float s = rall[(2 * hh) * 1024 + e] + rall[(2 * hh + 1) * 1024 + e];
        atomicAdd(&g_ctx[((long)b * HEADS + hh) * 1024 + e], s);
    }
}

// =============================================================================
// fp16 x fp16 cp.async GEMM (round-8 kernel, measured 64us) — final GEMM only
// =============================================================================
#define H_A_BUF 18432   // 128*144
#define H_B_BUF 17408   // 64*272
#define SMEM_H (2 * H_A_BUF + 2 * H_B_BUF)

__device__ __forceinline__ void g2s_tile_ff(uint32_t sb, int buf,
                                            const __half* Arow, const __half* Xb,
                                            long n0, int k0) {
    int tid = threadIdx.x;
    uint32_t abase = sb + buf * H_A_BUF;
    uint32_t bbase = sb + 2 * H_A_BUF + buf * H_B_BUF;
#pragma unroll
    for (int i = 0; i < 4; i++) {
        int f = i * 256 + tid;
        int r = f >> 3, c = f & 7;
        CP16(abase + r * 144 + c * 16, Arow + (long)r * 256 + k0 + c * 8);
    }
#pragma unroll
    for (int i = 0; i < 4; i++) {
        int f = i * 256 + tid;
        int r = f >> 4, c = f & 15;
        CP16(bbase + r * 272 + c * 16, Xb + (long)(k0 + r) * NPIX + n0 + c * 8);
    }
    asm volatile("cp.async.commit_group;" ::: "memory");
}

__global__ __launch_bounds__(256, 2)
void k_hgemm_ff(const __half* __restrict__ A, long sA,
                const __half* __restrict__ X, long sX,
                float* __restrict__ C, long sC,
                const float* __restrict__ bias)
{
    extern __shared__ char smem[];
    uint32_t sb = smem_u32(smem);

    int b = blockIdx.z;
    const __half* Ab = A + (long)b * sA + (long)blockIdx.y * 128 * 256;
    const __half* Xb = X + (long)b * sX;
    long n0 = (long)blockIdx.x * 128;
    int m0 = blockIdx.y * 128;

    int tid  = threadIdx.x;
    int wid  = tid >> 5, lane = tid & 31;
    int g4   = lane >> 2, q = lane & 3;
    int wm   = (wid >> 2) * 64;
    int wn   = (wid & 3) * 32;
    int rowoff = (lane & 7) + ((lane >> 3) & 1) * 8;
    int colsel = (lane >> 4) * 8;

    float acc[4][4][4];
#pragma unroll
    for (int i = 0; i < 4; i++)
#pragma unroll
        for (int j = 0; j < 4; j++)
#pragma unroll
            for (int r = 0; r < 4; r++) acc[i][j][r] = 0.f;

    g2s_tile_ff(sb, 0, Ab, Xb, n0, 0);

#pragma unroll 1
    for (int t = 0; t < 4; t++) {
        if (t < 3) g2s_tile_ff(sb, (t + 1) & 1, Ab, Xb, n0, (t + 1) * 64);
        if (t < 3) { asm volatile("cp.async.wait_group 1;" ::: "memory"); }
        else       { asm volatile("cp.async.wait_group 0;" ::: "memory"); }
        __syncthreads();

        uint32_t abase = sb + (t & 1) * H_A_BUF;
        uint32_t bbase = sb + 2 * H_A_BUF + (t & 1) * H_B_BUF;
#pragma unroll
        for (int ks = 0; ks < 64; ks += 16) {
            uint32_t af[4][4];
#pragma unroll
            for (int mf = 0; mf < 4; mf++) {
                uint32_t addr = abase + (uint32_t)((wm + mf * 16 + rowoff) * 144
                                                   + (ks + colsel) * 2);
                asm volatile(
                    "ldmatrix.sync.aligned.m8n8.x4.shared.b16 {%0,%1,%2,%3}, [%4];"
                    : "=r"(af[mf][0]), "=r"(af[mf][1]), "=r"(af[mf][2]), "=r"(af[mf][3])
                    : "r"(addr));
            }
            uint32_t bf[2][4];
#pragma unroll
            for (int np = 0; np < 2; np++) {
                uint32_t addr = bbase + (uint32_t)((ks + rowoff) * 272
                                                   + (wn + np * 16 + colsel) * 2);
                asm volatile(
                    "ldmatrix.sync.aligned.m8n8.x4.trans.shared.b16 {%0,%1,%2,%3}, [%4];"
                    : "=r"(bf[np][0]), "=r"(bf[np][1]), "=r"(bf[np][2]), "=r"(bf[np][3])
                    : "r"(addr));
            }
#pragma unroll
            for (int nf = 0; nf < 4; nf++) {
                uint32_t b0 = bf[nf >> 1][(nf & 1) * 2];
                uint32_t b1 = bf[nf >> 1][(nf & 1) * 2 + 1];
#pragma unroll
                for (int mf = 0; mf < 4; mf++)
                    HMMA(acc[mf][nf], af[mf][0], af[mf][1], af[mf][2], af[mf][3], b0, b1);
            }
        }
        __syncthreads();
    }

#pragma unroll
    for (int mf = 0; mf < 4; mf++) {
        long mrow = m0 + wm + mf * 16 + g4;
        float bv0 = bias[mrow];
        float bv1 = bias[mrow + 8];
#pragma unroll
        for (int nf = 0; nf < 4; nf++) {
            long nc = n0 + wn + nf * 8 + 2 * q;
            float2 v0 = { acc[mf][nf][0] + bv0, acc[mf][nf][1] + bv0 };
            float2 v1 = { acc[mf][nf][2] + bv1, acc[mf][nf][3] + bv1 };
            float* Cf = C + (long)b * sC;
            *(float2*)&Cf[mrow * NPIX + nc]       = v0;
            *(float2*)&Cf[(mrow + 8) * NPIX + nc] = v1;
        }
    }
}

// ---------------- tf32 mma SGEMM -> fp16 out (tiny fold GEMM, unchanged) -----
__global__ __launch_bounds__(256, 2)
void k_sgemm_tc(const float* __restrict__ A, long sA,
                const float* __restrict__ X, long sX,
                __half* __restrict__ C, long sC,
                int M, int K, int N)
{
    const int BM = 128, BN = 128, BK = 32;
    __shared__ uint32_t As[BK][BM + 4];
    __shared__ uint32_t Bs[BK][BN + 4];

    int b = blockIdx.z;
    const float* Ab = A + (long)b * sA;
    const float* Xb = X + (long)b * sX;
    __half*      Cb = C + (long)b * sC;
    int m0 = blockIdx.y * BM, n0 = blockIdx.x * BN;
    int tid  = threadIdx.x;
    int wid  = tid >> 5, lane = tid & 31;
    int g4   = lane >> 2, q = lane & 3;
    int wm   = (wid >> 2) * 64;
    int wn   = (wid & 3) * 32;

    float acc[4][4][4];
#pragma unroll
    for (int i = 0; i < 4; i++)
#pragma unroll
        for (int j = 0; j < 4; j++)
#pragma unroll
            for (int r = 0; r < 4; r++) acc[i][j][r] = 0.f;

    for (int k0 = 0; k0 < K; k0 += BK) {
#pragma unroll
        for (int i = 0; i < 4; i++) {
            int f  = i * 256 + tid;
            int m  = f >> 3, k4 = (f & 7) << 2;
            float4 v = *(const float4*)&Ab[(long)(m0 + m) * K + k0 + k4];
            As[k4 + 0][m] = cvt_tf32(v.x); As[k4 + 1][m] = cvt_tf32(v.y);
            As[k4 + 2][m] = cvt_tf32(v.z); As[k4 + 3][m] = cvt_tf32(v.w);
        }
#pragma unroll
        for (int i = 0; i < 4; i++) {
            int f  = i * 256 + tid;
            int kk = f >> 5, n4 = (f & 31) << 2;
            float4 v = *(const float4*)&Xb[(long)(k0 + kk) * N + n0 + n4];
            uint4 u;
            u.x = cvt_tf32(v.x); u.y = cvt_tf32(v.y);
            u.z = cvt_tf32(v.z); u.w = cvt_tf32(v.w);
            *(uint4*)&Bs[kk][n4] = u;
        }
        __syncthreads();

#pragma unroll
        for (int ks = 0; ks < BK; ks += 8) {
            uint32_t af[4][4];
#pragma unroll
            for (int mf = 0; mf < 4; mf++) {
                int mb = wm + mf * 16;
                af[mf][0] = As[ks + q    ][mb + g4    ];
                af[mf][1] = As[ks + q    ][mb + g4 + 8];
                af[mf][2] = As[ks + q + 4][mb + g4    ];
                af[mf][3] = As[ks + q + 4][mb + g4 + 8];
            }
#pragma unroll
            for (int nf = 0; nf < 4; nf++) {
                int nb = wn + nf * 8;
                uint32_t b0 = Bs[ks + q    ][nb + g4];
                uint32_t b1 = Bs[ks + q + 4][nb + g4];
#pragma unroll
                for (int mf = 0; mf < 4; mf++) {
                    asm volatile(
                        "mma.sync.aligned.m16n8k8.row.col.f32.tf32.tf32.f32 "
                        "{%0,%1,%2,%3},{%4,%5,%6,%7},{%8,%9},{%0,%1,%2,%3};"
                        : "+f"(acc[mf][nf][0]), "+f"(acc[mf][nf][1]),
                          "+f"(acc[mf][nf][2]), "+f"(acc[mf][nf][3])
                        : "r"(af[mf][0]), "r"(af[mf][1]),
                          "r"(af[mf][2]), "r"(af[mf][3]),
                          "r"(b0), "r"(b1));
                }
            }
        }
        __syncthreads();
    }

#pragma unroll
    for (int mf = 0; mf < 4; mf++) {
        int mrow = m0 + wm + mf * 16 + g4;
#pragma unroll
        for (int nf = 0; nf < 4; nf++) {
            int nc = n0 + wn + nf * 8 + 2 * q;
            *(__half2*)&Cb[(long)mrow * N + nc] =
                __floats2half2_rn(acc[mf][nf][0], acc[mf][nf][1]);
            *(__half2*)&Cb[(long)(mrow + 8) * N + nc] =
                __floats2half2_rn(acc[mf][nf][2], acc[mf][nf][3]);
        }
    }
}

// ---------------- fold: W_eff[b][o][h*32+d] = sum_e w_out[o][h*32+e]*ctxn[h][d][e]
__global__ __launch_bounds__(256)
void k_weff(const float* __restrict__ w_out)
{
    __shared__ float ctxn[HEADS][DH][DH + 1];
    __shared__ float zinv[HEADS * DH];
    int b = blockIdx.x, oc = blockIdx.y;
    int tid = threadIdx.x;
    if (tid < 128) zinv[tid] = 1.0f / g_z[b * 128 + tid];
    __syncthreads();
    for (int i = tid; i < 4096; i += 256) {
        int h = i >> 10, d = (i >> 5) & 31, e = i & 31;
        ctxn[h][d][e] = g_ctx[b * 4096 + i] * zinv[h * 32 + d];
    }
    __syncthreads();
    for (int i = tid; i < 8 * 128; i += 256) {
        int ol = i >> 7;
        int hd = i & 127;
        int h = hd >> 5, d = hd & 31;
        int o = oc * 8 + ol;
        const float* wrow = w_out + o * HID + h * 32;
        float s = 0.f;
#pragma unroll
        for (int e = 0; e < 32; e++) s = fmaf(wrow[e], ctxn[h][d][e], s);
        g_weff[((long)b * 256 + o) * HID + hd] = s;
    }
}

// ---------------- launch --------------------------------------------------
extern "C" void kernel_launch(void* const* d_in, const int* in_sizes, int n_in,
                              void* d_out, int out_size)
{
    const float *x = nullptr, *w_qkv = nullptr, *w_out = nullptr, *b_out = nullptr;
    for (int i = 0; i < n_in; i++) {
        const float* p = (const float*)d_in[i];
        if      (in_sizes[i] == BATCH * CIN * NPIX) x     = p;
        else if (in_sizes[i] == 3 * HID * CIN)      w_qkv = p;
        else if (in_sizes[i] == CIN * HID)          w_out = p;
        else if (in_sizes[i] == CIN)                b_out = p;
    }
    float* out = (float*)d_out;

    __half *xh, *wh, *wtoth;
    float *weff;
    cudaGetSymbolAddress((void**)&xh,    g_xh);
    cudaGetSymbolAddress((void**)&wh,    g_wh);
    cudaGetSymbolAddress((void**)&wtoth, g_wtoth);
    cudaGetSymbolAddress((void**)&weff,  g_weff);

    cudaFuncSetAttribute(k_fused1,
                         cudaFuncAttributeMaxDynamicSharedMemorySize, SMEM_F);
    cudaFuncSetAttribute(k_hgemm_ff,
                         cudaFuncAttributeMaxDynamicSharedMemorySize, SMEM_H);

    // 0) zero ALL accumulators + convert W_kv
    k_init<<<128, 256>>>(w_qkv + 128 * CIN);

    // 1) FUSED: kv-GEMM + exp + context + z; also emits fp16 x
    k_fused1<<<dim3(NPIX / 128, BATCH), 256, SMEM_F>>>(wh, x);

    // 2) fold w_out with normalized context -> W_eff (fp32)
    k_weff<<<dim3(BATCH, 32), 256>>>(w_out);

    // 3) W_total[b] = W_eff[b] @ W_q  -> fp16 wtot
    k_sgemm_tc<<<dim3(2, 2, BATCH), 256>>>(
        weff, (long)256 * HID,
        w_qkv, 0,
        wtoth, (long)256 * 256,
        256, HID, 256);

    // 4) y[b] = W_total[b] @ x[b] + b_out  (fast fp16 x fp16 GEMM)
    k_hgemm_ff<<<dim3(NPIX / 128, 2, BATCH), 256, SMEM_H>>>(
        wtoth, (long)256 * 256,
        xh, (long)CIN * NPIX,
        out, (long)256 * NPIX,
        b_out);
}